// round 11
// baseline (speedup 1.0000x reference)
#include <cuda_runtime.h>

#define BB   4
#define TQ   256
#define TV   2048
#define DD   512
#define UU   128
#define NROWS_Q (BB*TQ)          // 1024
#define NROWS_K (BB*TV)          // 8192
#define CTX_SIZE (NROWS_Q*UU)    // 131072
#define NCHUNK 32

typedef unsigned long long ull;

// Scratch (no cudaMalloc allowed)
__device__ float g_eq[NROWS_Q*UU];          // e^{2q}  0.5 MB
__device__ float g_k [NROWS_K*UU];          // raw k   4 MB
__device__ float g_ek[NROWS_K*UU];          // e^{2k}  4 MB
__device__ float g_scores[NROWS_Q*TV];      // 8 MB
__device__ float g_part[NCHUNK][CTX_SIZE];  // 16 MB

__device__ __forceinline__ float ex2f_(float x){ float y; asm("ex2.approx.f32 %0, %1;" : "=f"(y) : "f"(x)); return y; }
__device__ __forceinline__ float rcpf_(float x){ float y; asm("rcp.approx.f32 %0, %1;" : "=f"(y) : "f"(x)); return y; }

// Packed f32x2 (Blackwell): 2x fp32 FMA throughput, only reachable via PTX.
__device__ __forceinline__ ull pk2_(float lo, float hi){ ull r; asm("mov.b64 %0, {%1, %2};" : "=l"(r) : "f"(lo), "f"(hi)); return r; }
__device__ __forceinline__ void upk2_(ull v, float& lo, float& hi){ asm("mov.b64 {%0, %1}, %2;" : "=f"(lo), "=f"(hi) : "l"(v)); }
__device__ __forceinline__ ull fma2_(ull a, ull b, ull c){ ull d; asm("fma.rn.f32x2 %0, %1, %2, %3;" : "=l"(d) : "l"(a), "l"(b), "l"(c)); return d; }
__device__ __forceinline__ ull mul2_(ull a, ull b){ ull d; asm("mul.rn.f32x2 %0, %1, %2;" : "=l"(d) : "l"(a), "l"(b)); return d; }
__device__ __forceinline__ ull add2_(ull a, ull b){ ull d; asm("add.rn.f32x2 %0, %1, %2;" : "=l"(d) : "l"(a), "l"(b)); return d; }
#define ONE2 0x3F8000003F800000ULL

#define C2E 2.88539008177792681f   /* 2*log2(e) */

// ---------------------------------------------------------------------------
// Kernel 1: projections + exp epilogue, packed-FMA mainloop.
// C[M,128] = A[M,512] @ W[512,128] fp32. bid<32 -> q (store e^{2q} only),
// else -> k (store raw k AND e^{2k}). BM=32, BN=128, BK=16, thread 2m x (4 n-pairs).
// Grid 288 blocks (~2/SM) for occupancy.
// ---------------------------------------------------------------------------
__global__ __launch_bounds__(256) void proj_gemm(
    const float* __restrict__ dq, const float* __restrict__ ev,
    const float* __restrict__ W1, const float* __restrict__ W2)
{
    __shared__ __align__(16) float As[16][36];    // [kk][m], padded (144B rows)
    __shared__ __align__(16) float Bs[16][128];   // [kk][n]

    int bid = blockIdx.x;
    bool isq = (bid < 32);
    const float* A; const float* W; int mbase;
    if (isq) { A = dq; W = W1; mbase = bid * 32; }
    else     { A = ev; W = W2; mbase = (bid - 32) * 32; }

    int t  = threadIdx.x;
    int ty = t >> 4;          // 0..15 (row group: rows ty*2, ty*2+1)
    int tx = t & 15;          // 0..15 (col group)

    ull acc[2][4];
    #pragma unroll
    for (int i = 0; i < 2; i++)
        #pragma unroll
        for (int j = 0; j < 4; j++) acc[i][j] = 0ULL;

    for (int k0 = 0; k0 < DD; k0 += 16) {
        if (t < 128) {
            int lr = t >> 2;           // 0..31
            int lc = (t & 3) << 2;     // 0,4,8,12
            float4 av = *(const float4*)&A[(size_t)(mbase + lr) * DD + k0 + lc];
            As[lc + 0][lr] = av.x; As[lc + 1][lr] = av.y;
            As[lc + 2][lr] = av.z; As[lc + 3][lr] = av.w;
        }
        {
            int i0 = t, i1 = t + 256;
            *(float4*)&Bs[i0 >> 5][(i0 & 31) << 2] =
                *(const float4*)&W[(size_t)(k0 + (i0 >> 5)) * UU + ((i0 & 31) << 2)];
            *(float4*)&Bs[i1 >> 5][(i1 & 31) << 2] =
                *(const float4*)&W[(size_t)(k0 + (i1 >> 5)) * UU + ((i1 & 31) << 2)];
        }
        __syncthreads();

        #pragma unroll
        for (int kk = 0; kk < 16; kk++) {
            float2 a2 = *(const float2*)&As[kk][ty * 2];
            ulonglong2 b0 = *(const ulonglong2*)&Bs[kk][tx * 4];
            ulonglong2 b1 = *(const ulonglong2*)&Bs[kk][64 + tx * 4];
            ull a0 = pk2_(a2.x, a2.x);
            ull a1 = pk2_(a2.y, a2.y);
            acc[0][0] = fma2_(a0, b0.x, acc[0][0]);
            acc[0][1] = fma2_(a0, b0.y, acc[0][1]);
            acc[0][2] = fma2_(a0, b1.x, acc[0][2]);
            acc[0][3] = fma2_(a0, b1.y, acc[0][3]);
            acc[1][0] = fma2_(a1, b0.x, acc[1][0]);
            acc[1][1] = fma2_(a1, b0.y, acc[1][1]);
            acc[1][2] = fma2_(a1, b1.x, acc[1][2]);
            acc[1][3] = fma2_(a1, b1.y, acc[1][3]);
        }
        __syncthreads();
    }

    #pragma unroll
    for (int i = 0; i < 2; i++) {
        float c[8];
        upk2_(acc[i][0], c[0], c[1]); upk2_(acc[i][1], c[2], c[3]);
        upk2_(acc[i][2], c[4], c[5]); upk2_(acc[i][3], c[6], c[7]);
        int row = mbase + ty * 2 + i;
        size_t o0 = (size_t)row * UU + tx * 4;
        size_t o1 = o0 + 64;
        float4 e0 = make_float4(ex2f_(c[0]*C2E), ex2f_(c[1]*C2E),
                                ex2f_(c[2]*C2E), ex2f_(c[3]*C2E));
        float4 e1 = make_float4(ex2f_(c[4]*C2E), ex2f_(c[5]*C2E),
                                ex2f_(c[6]*C2E), ex2f_(c[7]*C2E));
        if (isq) {
            *(float4*)&g_eq[o0] = e0;
            *(float4*)&g_eq[o1] = e1;
        } else {
            *(float4*)&g_k[o0] = make_float4(c[0], c[1], c[2], c[3]);
            *(float4*)&g_k[o1] = make_float4(c[4], c[5], c[6], c[7]);
            *(float4*)&g_ek[o0] = e0;
            *(float4*)&g_ek[o1] = e1;
        }
    }
}

// ---------------------------------------------------------------------------
// Kernel 2: scores, factorized exp + pairwise rcp-combine + packed FMA.
//   s0/(1+a0) + s1/(1+a1) = [sab + s0*a1 + s1*a0] / [(1+a0)(1+a1)]
// -> 1 RCP per 2 u. u-swizzled tiles (u0,u2,u1,u3): one LDS.128 gives both
// f32x2 operand pairs. Block 32q x 32v, 64 thr; thread 4q x 4v (16 bodies
// per uq). STRIDED row ownership (q = qg+8*qi, v = vg+8*vj): LDS.128 row
// spacing 528B = 16 mod 128 -> conflict-free across the 8 vg / broadcast qg.
// score' = -2*sum (const Sum(scale) shift dropped; softmax shift-invariant,
// scores not an output). smem 34.5KB -> 6 blocks/SM, 12 warps/SM.
// ---------------------------------------------------------------------------
__global__ __launch_bounds__(64, 6) void scores_kernel(const float* __restrict__ scale)
{
    __shared__ __align__(16) float Qs[32][132];    // stride 132: 16B-aligned rows
    __shared__ __align__(16) float Ks[32][132];
    __shared__ __align__(8)  float2 Sa[32], Sb[32], Sab[32];

    int b  = blockIdx.z;
    int qt = blockIdx.y;
    int vt = blockIdx.x;
    int t  = threadIdx.x;

    const float* qg_ = g_eq + (size_t)(b * TQ + qt * 32) * UU;
    const float* kg_ = g_ek + (size_t)(b * TV + vt * 32) * UU;

    #pragma unroll
    for (int j = 0; j < 16; j++) {
        int i = t + j * 64;
        int r = i >> 5, c = (i & 31) << 2;
        float4 x = *(const float4*)&qg_[(size_t)r * UU + c];
        *(float4*)&Qs[r][c] = make_float4(x.x, x.z, x.y, x.w);   // u-swizzle
        float4 y = *(const float4*)&kg_[(size_t)r * UU + c];
        *(float4*)&Ks[r][c] = make_float4(y.x, y.z, y.y, y.w);
    }
    if (t < 32) {
        float4 s = *(const float4*)&scale[t * 4];
        Sa[t]  = make_float2(s.x, s.z);
        Sb[t]  = make_float2(s.y, s.w);
        Sab[t] = make_float2(s.x + s.y, s.z + s.w);
    }
    __syncthreads();

    int vg = t & 7;           // v rows vg, vg+8, vg+16, vg+24
    int qg = t >> 3;          // q rows qg, qg+8, qg+16, qg+24

    ull acc[4][4];            // [qi][vj]
    #pragma unroll
    for (int i = 0; i < 4; i++)
        #pragma unroll
        for (int j = 0; j < 4; j++) acc[i][j] = 0ULL;

    #pragma unroll 2
    for (int uq = 0; uq < 32; uq++) {
        ull sa  = *(const ull*)&Sa[uq];
        ull sb  = *(const ull*)&Sb[uq];
        ull sab = *(const ull*)&Sab[uq];
        ulonglong2 k4[4];
        #pragma unroll
        for (int vj = 0; vj < 4; vj++)
            k4[vj] = *(const ulonglong2*)&Ks[vg + 8 * vj][uq * 4];
        #pragma unroll
        for (int qi = 0; qi < 4; qi++) {
            ulonglong2 q4 = *(const ulonglong2*)&Qs[qg + 8 * qi][uq * 4];
            #pragma unroll
            for (int vj = 0; vj < 4; vj++) {
                ull A = mul2_(q4.x, k4[vj].x);    // (a_u0, a_u2)
                ull B = mul2_(q4.y, k4[vj].y);    // (a_u1, a_u3)
                ull U = add2_(A, ONE2);
                ull P = fma2_(U, B, U);           // (1+a)(1+b)
                ull N = fma2_(sb, A, sab);
                N = fma2_(sa, B, N);
                float pl, ph; upk2_(P, pl, ph);
                ull R = pk2_(rcpf_(pl), rcpf_(ph));
                acc[qi][vj] = fma2_(N, R, acc[qi][vj]);
            }
        }
    }

    #pragma unroll
    for (int qi = 0; qi < 4; qi++) {
        float* out = g_scores + (size_t)(b * TQ + qt * 32 + qg + 8 * qi) * TV + vt * 32 + vg;
        #pragma unroll
        for (int vj = 0; vj < 4; vj++) {
            float lo, hi; upk2_(acc[qi][vj], lo, hi);
            out[8 * vj] = -2.0f * (lo + hi);
        }
    }
}

// ---------------------------------------------------------------------------
// Kernel 3: row softmax over Tv=2048. One block per (b,q) row.
// ---------------------------------------------------------------------------
__global__ __launch_bounds__(256) void softmax_kernel(float* __restrict__ wout)
{
    __shared__ float red[8];
    int row = blockIdx.x;
    int t   = threadIdx.x;

    const float4* in4 = (const float4*)(g_scores + (size_t)row * TV);
    float4 a = in4[t];
    float4 b = in4[t + 256];

    float m = fmaxf(fmaxf(fmaxf(a.x, a.y), fmaxf(a.z, a.w)),
                    fmaxf(fmaxf(b.x, b.y), fmaxf(b.z, b.w)));
    #pragma unroll
    for (int off = 16; off; off >>= 1)
        m = fmaxf(m, __shfl_xor_sync(0xffffffffu, m, off));
    if ((t & 31) == 0) red[t >> 5] = m;
    __syncthreads();
    m = red[0];
    #pragma unroll
    for (int i = 1; i < 8; i++) m = fmaxf(m, red[i]);

    const float L2E = 1.44269504088896341f;
    float e0 = ex2f_((a.x - m) * L2E), e1 = ex2f_((a.y - m) * L2E);
    float e2 = ex2f_((a.z - m) * L2E), e3 = ex2f_((a.w - m) * L2E);
    float e4 = ex2f_((b.x - m) * L2E), e5 = ex2f_((b.y - m) * L2E);
    float e6 = ex2f_((b.z - m) * L2E), e7 = ex2f_((b.w - m) * L2E);
    float s = ((e0 + e1) + (e2 + e3)) + ((e4 + e5) + (e6 + e7));
    #pragma unroll
    for (int off = 16; off; off >>= 1)
        s += __shfl_xor_sync(0xffffffffu, s, off);
    __syncthreads();
    if ((t & 31) == 0) red[t >> 5] = s;
    __syncthreads();
    float tot = 0.0f;
    #pragma unroll
    for (int i = 0; i < 8; i++) tot += red[i];
    float inv = rcpf_(tot);

    float4* o4 = (float4*)(wout + (size_t)row * TV);
    o4[t]       = make_float4(e0 * inv, e1 * inv, e2 * inv, e3 * inv);
    o4[t + 256] = make_float4(e4 * inv, e5 * inv, e6 * inv, e7 * inv);
}

// ---------------------------------------------------------------------------
// Kernel 4: context partials, packed over q-pairs, w pre-packed in smem.
// ctx[b,q,u] = sum_v w[b,q,v]*k[b,v,u].
// Grid (32 v-chunks of 64, 32 q-tiles of 32) = 1024 blocks. Block 128 thr:
// ug = t&31 (u-quad), qg = t>>5 (8 q rows = 4 q-pairs). 16 packed accs.
// v-tile 32 (smem 20.5KB); launch_bounds(128,6) caps regs for ~6 blocks/SM.
// ---------------------------------------------------------------------------
__global__ __launch_bounds__(128, 6) void ctx_partial(const float* __restrict__ wts)
{
    __shared__ __align__(16) float Ks2[32][128];   // [v][u] 16KB
    __shared__ __align__(16) ull   Wp[32][18];     // [v][qpair]; stride 18 -> 16B-aligned rows

    int chunk = blockIdx.x;          // 0..31 -> v in [chunk*64, +64)
    int rt    = blockIdx.y;          // 0..31 -> q rows rt*32..+31
    int r0    = rt * 32;             // global row base (b*256+q)
    int bbb   = r0 >> 8;             // batch
    int t     = threadIdx.x;
    int ug    = t & 31;              // u = ug*4..+3
    int qg    = t >> 5;              // q-pairs qg*4..+3  (q rows qg*8..+7)

    ull acc[4][4];                   // [u][qpair]
    #pragma unroll
    for (int u = 0; u < 4; u++)
        #pragma unroll
        for (int p = 0; p < 4; p++) acc[u][p] = 0ULL;

    #pragma unroll 1
    for (int vt = 0; vt < 2; vt++) {
        int vbase = chunk * 64 + vt * 32;
        #pragma unroll
        for (int j = 0; j < 8; j++) {
            int i = t + j * 128;                  // 0..1023
            int v = i >> 5, c = (i & 31) << 2;
            *(float4*)&Ks2[v][c] =
                *(const float4*)&g_k[(size_t)(bbb * TV + vbase + v) * UU + c];
        }
        #pragma unroll
        for (int j = 0; j < 4; j++) {
            int i = t + j * 128;                  // 0..511
            int qp = i >> 5, v = i & 31;          // qp 0..15, v 0..31
            const float* wp = &wts[(size_t)(r0 + qp * 2) * TV + vbase + v];
            Wp[v][qp] = pk2_(wp[0], wp[TV]);
        }
        __syncthreads();

        #pragma unroll 4
        for (int v = 0; v < 32; v++) {
            float4 kf = *(const float4*)&Ks2[v][ug * 4];
            ull k0 = pk2_(kf.x, kf.x), k1 = pk2_(kf.y, kf.y);
            ull k2 = pk2_(kf.z, kf.z), k3 = pk2_(kf.w, kf.w);
            ulonglong2 wa = *(const ulonglong2*)&Wp[v][qg * 4];
            ulonglong2 wb = *(const ulonglong2*)&Wp[v][qg * 4 + 2];
            acc[0][0] = fma2_(k0, wa.x, acc[0][0]);
            acc[1][0] = fma2_(k1, wa.x, acc[1][0]);
            acc[2][0] = fma2_(k2, wa.x, acc[2][0]);
            acc[3][0] = fma2_(k3, wa.x, acc[3][0]);
            acc[0][1] = fma2_(k0, wa.y, acc[0][1]);
            acc[1][1] = fma2_(k1, wa.y, acc[1][1]);
            acc[2][1] = fma2_(k2, wa.y, acc[2][1]);
            acc[3][1] = fma2_(k3, wa.y, acc[3][1]);
            acc[0][2] = fma2_(k0, wb.x, acc[0][2]);
            acc[1][2] = fma2_(k1, wb.x, acc[1][2]);
            acc[2][2] = fma2_(k2, wb.x, acc[2][2]);
            acc[3][2] = fma2_(k3, wb.x, acc[3][2]);
            acc[0][3] = fma2_(k0, wb.y, acc[0][3]);
            acc[1][3] = fma2_(k1, wb.y, acc[1][3]);
            acc[2][3] = fma2_(k2, wb.y, acc[2][3]);
            acc[3][3] = fma2_(k3, wb.y, acc[3][3]);
        }
        __syncthreads();
    }

    #pragma unroll
    for (int p = 0; p < 4; p++) {
        float lo[4], hi[4];
        upk2_(acc[0][p], lo[0], hi[0]);
        upk2_(acc[1][p], lo[1], hi[1]);
        upk2_(acc[2][p], lo[2], hi[2]);
        upk2_(acc[3][p], lo[3], hi[3]);
        int q0 = r0 + qg * 8 + p * 2;
        *(float4*)&g_part[chunk][(size_t)q0 * UU + ug * 4] =
            make_float4(lo[0], lo[1], lo[2], lo[3]);
        *(float4*)&g_part[chunk][(size_t)(q0 + 1) * UU + ug * 4] =
            make_float4(hi[0], hi[1], hi[2], hi[3]);
    }
}

// ---------------------------------------------------------------------------
// Kernel 5: reduce 32 partials -> context into d_out[0 .. CTX_SIZE)
// ---------------------------------------------------------------------------
__global__ __launch_bounds__(256) void ctx_reduce(float* __restrict__ out)
{
    int i = blockIdx.x * 256 + threadIdx.x;   // float4 index, 32768 total
    float4 s = ((const float4*)g_part[0])[i];
    #pragma unroll
    for (int c = 1; c < NCHUNK; c++) {
        float4 p = ((const float4*)g_part[c])[i];
        s.x += p.x; s.y += p.y; s.z += p.z; s.w += p.w;
    }
    ((float4*)out)[i] = s;
}

extern "C" void kernel_launch(void* const* d_in, const int* in_sizes, int n_in,
                              void* d_out, int out_size)
{
    (void)in_sizes; (void)n_in; (void)out_size;
    const float* dq    = (const float*)d_in[0];   // [4,256,512]
    const float* ev    = (const float*)d_in[1];   // [4,2048,512]
    const float* W1    = (const float*)d_in[2];   // [512,128]
    const float* W2    = (const float*)d_in[3];   // [512,128]
    const float* scale = (const float*)d_in[4];   // [128]
    float* out  = (float*)d_out;                  // context [131072] ++ weights [2097152]
    float* wout = out + CTX_SIZE;

    proj_gemm<<<288, 256>>>(dq, ev, W1, W2);
    scores_kernel<<<dim3(TV / 32, TQ / 32, BB), 64>>>(scale);
    softmax_kernel<<<NROWS_Q, 256>>>(wout);
    ctx_partial<<<dim3(NCHUNK, 32), 128>>>(wout);
    ctx_reduce<<<CTX_SIZE / 4 / 256, 256>>>(out);
}

// round 12
// speedup vs baseline: 1.0793x; 1.0793x over previous
#include <cuda_runtime.h>

#define BB   4
#define TQ   256
#define TV   2048
#define DD   512
#define UU   128
#define NROWS_Q (BB*TQ)          // 1024
#define NROWS_K (BB*TV)          // 8192
#define CTX_SIZE (NROWS_Q*UU)    // 131072
#define NCHUNK 32

typedef unsigned long long ull;

// Scratch (no cudaMalloc allowed)
__device__ float g_eq[NROWS_Q*UU];          // e^{2q}  0.5 MB
__device__ float g_k [NROWS_K*UU];          // raw k   4 MB
__device__ float g_ek[NROWS_K*UU];          // e^{2k}  4 MB
__device__ float g_scores[NROWS_Q*TV];      // 8 MB
__device__ float g_part[NCHUNK][CTX_SIZE];  // 16 MB

__device__ __forceinline__ float ex2f_(float x){ float y; asm("ex2.approx.f32 %0, %1;" : "=f"(y) : "f"(x)); return y; }
__device__ __forceinline__ float rcpf_(float x){ float y; asm("rcp.approx.f32 %0, %1;" : "=f"(y) : "f"(x)); return y; }

// Packed f32x2 (Blackwell): 2x fp32 FMA throughput, only reachable via PTX.
__device__ __forceinline__ ull pk2_(float lo, float hi){ ull r; asm("mov.b64 %0, {%1, %2};" : "=l"(r) : "f"(lo), "f"(hi)); return r; }
__device__ __forceinline__ void upk2_(ull v, float& lo, float& hi){ asm("mov.b64 {%0, %1}, %2;" : "=f"(lo), "=f"(hi) : "l"(v)); }
__device__ __forceinline__ ull fma2_(ull a, ull b, ull c){ ull d; asm("fma.rn.f32x2 %0, %1, %2, %3;" : "=l"(d) : "l"(a), "l"(b), "l"(c)); return d; }
__device__ __forceinline__ ull mul2_(ull a, ull b){ ull d; asm("mul.rn.f32x2 %0, %1, %2;" : "=l"(d) : "l"(a), "l"(b)); return d; }
__device__ __forceinline__ ull add2_(ull a, ull b){ ull d; asm("add.rn.f32x2 %0, %1, %2;" : "=l"(d) : "l"(a), "l"(b)); return d; }
#define ONE2 0x3F8000003F800000ULL

#define C2E 2.88539008177792681f   /* 2*log2(e) */

// ---------------------------------------------------------------------------
// Kernel 1: projections + exp epilogue, packed-FMA, double-buffered smem.
// C[M,128] = A[M,512] @ W[512,128] fp32. bid<16 -> q (store e^{2q} only),
// else -> k (store raw k AND e^{2k}). BM=64, BN=128, BK=16, thread 4m x 8n.
// One __syncthreads per k-step; GMEM loads overlap the mainloop.
// ---------------------------------------------------------------------------
__global__ __launch_bounds__(256) void proj_gemm(
    const float* __restrict__ dq, const float* __restrict__ ev,
    const float* __restrict__ W1, const float* __restrict__ W2)
{
    __shared__ __align__(16) float As[2][16][68];    // [buf][kk][m]
    __shared__ __align__(16) float Bs[2][16][128];   // [buf][kk][n]

    int bid = blockIdx.x;
    bool isq = (bid < 16);
    const float* A; const float* W; int mbase;
    if (isq) { A = dq; W = W1; mbase = bid * 64; }
    else     { A = ev; W = W2; mbase = (bid - 16) * 64; }

    int t  = threadIdx.x;
    int ty = t >> 4;          // 0..15 (row group)
    int tx = t & 15;          // 0..15 (col group)
    int lr = t >> 2;          // 0..63 (A load row)
    int lc = (t & 3) << 2;    // 0,4,8,12 (A load col quad)
    int br0 = t >> 5;         // B row for i0
    int bc  = (t & 31) << 2;  // B col quad

    ull acc[4][4];
    #pragma unroll
    for (int i = 0; i < 4; i++)
        #pragma unroll
        for (int j = 0; j < 4; j++) acc[i][j] = 0ULL;

    // prologue: tile 0
    {
        float4 av = *(const float4*)&A[(size_t)(mbase + lr) * DD + lc];
        As[0][lc + 0][lr] = av.x; As[0][lc + 1][lr] = av.y;
        As[0][lc + 2][lr] = av.z; As[0][lc + 3][lr] = av.w;
        *(float4*)&Bs[0][br0][bc]     = *(const float4*)&W[(size_t)br0 * UU + bc];
        *(float4*)&Bs[0][br0 + 8][bc] = *(const float4*)&W[(size_t)(br0 + 8) * UU + bc];
    }
    __syncthreads();

    int buf = 0;
    for (int k0 = 0; k0 < DD; k0 += 16, buf ^= 1) {
        float4 nav, nb0, nb1;
        bool more = (k0 + 16 < DD);
        if (more) {
            nav = *(const float4*)&A[(size_t)(mbase + lr) * DD + k0 + 16 + lc];
            nb0 = *(const float4*)&W[(size_t)(k0 + 16 + br0) * UU + bc];
            nb1 = *(const float4*)&W[(size_t)(k0 + 24 + br0) * UU + bc];
        }

        #pragma unroll
        for (int kk = 0; kk < 16; kk++) {
            float4 a4 = *(const float4*)&As[buf][kk][ty * 4];
            ulonglong2 b0 = *(const ulonglong2*)&Bs[buf][kk][tx * 4];
            ulonglong2 b1 = *(const ulonglong2*)&Bs[buf][kk][64 + tx * 4];
            float a[4] = {a4.x, a4.y, a4.z, a4.w};
            #pragma unroll
            for (int i = 0; i < 4; i++) {
                ull ad = pk2_(a[i], a[i]);
                acc[i][0] = fma2_(ad, b0.x, acc[i][0]);
                acc[i][1] = fma2_(ad, b0.y, acc[i][1]);
                acc[i][2] = fma2_(ad, b1.x, acc[i][2]);
                acc[i][3] = fma2_(ad, b1.y, acc[i][3]);
            }
        }

        if (more) {
            int nb = buf ^ 1;
            As[nb][lc + 0][lr] = nav.x; As[nb][lc + 1][lr] = nav.y;
            As[nb][lc + 2][lr] = nav.z; As[nb][lc + 3][lr] = nav.w;
            *(float4*)&Bs[nb][br0][bc]     = nb0;
            *(float4*)&Bs[nb][br0 + 8][bc] = nb1;
        }
        __syncthreads();
    }

    #pragma unroll
    for (int i = 0; i < 4; i++) {
        float c[8];
        upk2_(acc[i][0], c[0], c[1]); upk2_(acc[i][1], c[2], c[3]);
        upk2_(acc[i][2], c[4], c[5]); upk2_(acc[i][3], c[6], c[7]);
        int row = mbase + ty * 4 + i;
        size_t o0 = (size_t)row * UU + tx * 4;
        size_t o1 = o0 + 64;
        float4 e0 = make_float4(ex2f_(c[0]*C2E), ex2f_(c[1]*C2E),
                                ex2f_(c[2]*C2E), ex2f_(c[3]*C2E));
        float4 e1 = make_float4(ex2f_(c[4]*C2E), ex2f_(c[5]*C2E),
                                ex2f_(c[6]*C2E), ex2f_(c[7]*C2E));
        if (isq) {
            *(float4*)&g_eq[o0] = e0;
            *(float4*)&g_eq[o1] = e1;
        } else {
            *(float4*)&g_k[o0] = make_float4(c[0], c[1], c[2], c[3]);
            *(float4*)&g_k[o1] = make_float4(c[4], c[5], c[6], c[7]);
            *(float4*)&g_ek[o0] = e0;
            *(float4*)&g_ek[o1] = e1;
        }
    }
}

// ---------------------------------------------------------------------------
// Kernel 2: scores, factorized exp + pairwise rcp-combine + packed FMA.
// (Exact config of the best 140.2us run: 128 thr, 32q x 32v, thread 2q x 4v.)
//   s0/(1+a0) + s1/(1+a1) = [sab + s0*a1 + s1*a0] / [(1+a0)(1+a1)]
// -> 1 RCP per 2 u. u-swizzled tiles (u0,u2,u1,u3).
// ---------------------------------------------------------------------------
__global__ __launch_bounds__(128) void scores_kernel(const float* __restrict__ scale)
{
    __shared__ __align__(16) float Qs[32][132];    // stride 132: 16B-aligned rows
    __shared__ __align__(16) float Ks[32][132];
    __shared__ __align__(8)  float2 Sa[32], Sb[32], Sab[32];

    int b  = blockIdx.z;
    int qt = blockIdx.y;
    int vt = blockIdx.x;
    int t  = threadIdx.x;

    const float* qg_ = g_eq + (size_t)(b * TQ + qt * 32) * UU;
    const float* kg_ = g_ek + (size_t)(b * TV + vt * 32) * UU;

    #pragma unroll
    for (int j = 0; j < 8; j++) {
        int i = t + j * 128;
        int r = i >> 5, c = (i & 31) << 2;
        float4 x = *(const float4*)&qg_[(size_t)r * UU + c];
        *(float4*)&Qs[r][c] = make_float4(x.x, x.z, x.y, x.w);   // u-swizzle
        float4 y = *(const float4*)&kg_[(size_t)r * UU + c];
        *(float4*)&Ks[r][c] = make_float4(y.x, y.z, y.y, y.w);
    }
    if (t < 32) {
        float4 s = *(const float4*)&scale[t * 4];
        Sa[t]  = make_float2(s.x, s.z);
        Sb[t]  = make_float2(s.y, s.w);
        Sab[t] = make_float2(s.x + s.y, s.z + s.w);
    }
    __syncthreads();

    int vg = t & 7;           // v rows vg*4..+3
    int qg = t >> 3;          // q rows qg*2..+1
    int v0 = vg * 4, q0 = qg * 2;

    ull acc[2][4];
    #pragma unroll
    for (int i = 0; i < 2; i++)
        #pragma unroll
        for (int j = 0; j < 4; j++) acc[i][j] = 0ULL;

    #pragma unroll 2
    for (int uq = 0; uq < 32; uq++) {
        ull sa  = *(const ull*)&Sa[uq];
        ull sb  = *(const ull*)&Sb[uq];
        ull sab = *(const ull*)&Sab[uq];
        ulonglong2 k4[4];
        #pragma unroll
        for (int v = 0; v < 4; v++)
            k4[v] = *(const ulonglong2*)&Ks[v0 + v][uq * 4];
        #pragma unroll
        for (int qi = 0; qi < 2; qi++) {
            ulonglong2 q4 = *(const ulonglong2*)&Qs[q0 + qi][uq * 4];
            #pragma unroll
            for (int v = 0; v < 4; v++) {
                ull A = mul2_(q4.x, k4[v].x);     // (a_u0, a_u2)
                ull B = mul2_(q4.y, k4[v].y);     // (a_u1, a_u3)
                ull U = add2_(A, ONE2);
                ull P = fma2_(U, B, U);           // (1+a)(1+b)
                ull N = fma2_(sb, A, sab);
                N = fma2_(sa, B, N);
                float pl, ph; upk2_(P, pl, ph);
                ull R = pk2_(rcpf_(pl), rcpf_(ph));
                acc[qi][v] = fma2_(N, R, acc[qi][v]);
            }
        }
    }

    #pragma unroll
    for (int qi = 0; qi < 2; qi++) {
        float* out = g_scores + (size_t)(b * TQ + qt * 32 + q0 + qi) * TV + vt * 32 + v0;
        #pragma unroll
        for (int v = 0; v < 4; v++) {
            float lo, hi; upk2_(acc[qi][v], lo, hi);
            out[v] = -2.0f * (lo + hi);
        }
    }
}

// ---------------------------------------------------------------------------
// Kernel 3: row softmax over Tv=2048. One block per (b,q) row.
// ---------------------------------------------------------------------------
__global__ __launch_bounds__(256) void softmax_kernel(float* __restrict__ wout)
{
    __shared__ float red[8];
    int row = blockIdx.x;
    int t   = threadIdx.x;

    const float4* in4 = (const float4*)(g_scores + (size_t)row * TV);
    float4 a = in4[t];
    float4 b = in4[t + 256];

    float m = fmaxf(fmaxf(fmaxf(a.x, a.y), fmaxf(a.z, a.w)),
                    fmaxf(fmaxf(b.x, b.y), fmaxf(b.z, b.w)));
    #pragma unroll
    for (int off = 16; off; off >>= 1)
        m = fmaxf(m, __shfl_xor_sync(0xffffffffu, m, off));
    if ((t & 31) == 0) red[t >> 5] = m;
    __syncthreads();
    m = red[0];
    #pragma unroll
    for (int i = 1; i < 8; i++) m = fmaxf(m, red[i]);

    const float L2E = 1.44269504088896341f;
    float e0 = ex2f_((a.x - m) * L2E), e1 = ex2f_((a.y - m) * L2E);
    float e2 = ex2f_((a.z - m) * L2E), e3 = ex2f_((a.w - m) * L2E);
    float e4 = ex2f_((b.x - m) * L2E), e5 = ex2f_((b.y - m) * L2E);
    float e6 = ex2f_((b.z - m) * L2E), e7 = ex2f_((b.w - m) * L2E);
    float s = ((e0 + e1) + (e2 + e3)) + ((e4 + e5) + (e6 + e7));
    #pragma unroll
    for (int off = 16; off; off >>= 1)
        s += __shfl_xor_sync(0xffffffffu, s, off);
    __syncthreads();
    if ((t & 31) == 0) red[t >> 5] = s;
    __syncthreads();
    float tot = 0.0f;
    #pragma unroll
    for (int i = 0; i < 8; i++) tot += red[i];
    float inv = rcpf_(tot);

    float4* o4 = (float4*)(wout + (size_t)row * TV);
    o4[t]       = make_float4(e0 * inv, e1 * inv, e2 * inv, e3 * inv);
    o4[t + 256] = make_float4(e4 * inv, e5 * inv, e6 * inv, e7 * inv);
}

// ---------------------------------------------------------------------------
// Kernel 4: context partials, q-tile 64 so each k-row LDS feeds 2x the FMA.
// ctx[b,q,u] = sum_v w[b,q,v]*k[b,v,u].
// Grid (32 v-chunks of 64, 16 q-tiles of 64) = 512 blocks (single wave at
// 4/SM). Block 128 thr: ug = t&31 (u-quad), qg = t>>5 (16 q rows = 8 pairs).
// 32 packed accs. Per v per warp: 1 LDS.128 k + 4 broadcast LDS.128 w for
// 32 fma2 -> FMA-bound (was LDS-bound at 21us).
// ---------------------------------------------------------------------------
__global__ __launch_bounds__(128, 4) void ctx_partial(const float* __restrict__ wts)
{
    __shared__ __align__(16) float Ks2[32][128];   // [v][u] 16KB
    __shared__ __align__(16) ull   Wp[32][34];     // [v][qpair 0..31]; 272B rows

    int chunk = blockIdx.x;          // 0..31 -> v in [chunk*64, +64)
    int rt    = blockIdx.y;          // 0..15 -> q rows rt*64..+63
    int r0    = rt * 64;             // global row base (b*256+q)
    int bbb   = r0 >> 8;             // batch
    int t     = threadIdx.x;
    int ug    = t & 31;              // u = ug*4..+3
    int qg    = t >> 5;              // q-pairs qg*8..+7 (q rows qg*16..+15)

    ull acc[4][8];                   // [u][qpair]
    #pragma unroll
    for (int u = 0; u < 4; u++)
        #pragma unroll
        for (int p = 0; p < 8; p++) acc[u][p] = 0ULL;

    #pragma unroll 1
    for (int vt = 0; vt < 2; vt++) {
        int vbase = chunk * 64 + vt * 32;
        #pragma unroll
        for (int j = 0; j < 8; j++) {
            int i = t + j * 128;                  // 0..1023
            int v = i >> 5, c = (i & 31) << 2;
            *(float4*)&Ks2[v][c] =
                *(const float4*)&g_k[(size_t)(bbb * TV + vbase + v) * UU + c];
        }
        #pragma unroll
        for (int j = 0; j < 8; j++) {
            int i = t + j * 128;                  // 0..1023
            int qp = i >> 5, v = i & 31;          // qp 0..31, v 0..31
            const float* wp = &wts[(size_t)(r0 + qp * 2) * TV + vbase + v];
            Wp[v][qp] = pk2_(wp[0], wp[TV]);
        }
        __syncthreads();

        #pragma unroll 4
        for (int v = 0; v < 32; v++) {
            float4 kf = *(const float4*)&Ks2[v][ug * 4];
            ull k0 = pk2_(kf.x, kf.x), k1 = pk2_(kf.y, kf.y);
            ull k2 = pk2_(kf.z, kf.z), k3 = pk2_(kf.w, kf.w);
            ulonglong2 wa = *(const ulonglong2*)&Wp[v][qg * 8];
            ulonglong2 wb = *(const ulonglong2*)&Wp[v][qg * 8 + 2];
            ulonglong2 wc = *(const ulonglong2*)&Wp[v][qg * 8 + 4];
            ulonglong2 wd = *(const ulonglong2*)&Wp[v][qg * 8 + 6];
            acc[0][0] = fma2_(k0, wa.x, acc[0][0]);
            acc[1][0] = fma2_(k1, wa.x, acc[1][0]);
            acc[2][0] = fma2_(k2, wa.x, acc[2][0]);
            acc[3][0] = fma2_(k3, wa.x, acc[3][0]);
            acc[0][1] = fma2_(k0, wa.y, acc[0][1]);
            acc[1][1] = fma2_(k1, wa.y, acc[1][1]);
            acc[2][1] = fma2_(k2, wa.y, acc[2][1]);
            acc[3][1] = fma2_(k3, wa.y, acc[3][1]);
            acc[0][2] = fma2_(k0, wb.x, acc[0][2]);
            acc[1][2] = fma2_(k1, wb.x, acc[1][2]);
            acc[2][2] = fma2_(k2, wb.x, acc[2][2]);
            acc[3][2] = fma2_(k3, wb.x, acc[3][2]);
            acc[0][3] = fma2_(k0, wb.y, acc[0][3]);
            acc[1][3] = fma2_(k1, wb.y, acc[1][3]);
            acc[2][3] = fma2_(k2, wb.y, acc[2][3]);
            acc[3][3] = fma2_(k3, wb.y, acc[3][3]);
            acc[0][4] = fma2_(k0, wc.x, acc[0][4]);
            acc[1][4] = fma2_(k1, wc.x, acc[1][4]);
            acc[2][4] = fma2_(k2, wc.x, acc[2][4]);
            acc[3][4] = fma2_(k3, wc.x, acc[3][4]);
            acc[0][5] = fma2_(k0, wc.y, acc[0][5]);
            acc[1][5] = fma2_(k1, wc.y, acc[1][5]);
            acc[2][5] = fma2_(k2, wc.y, acc[2][5]);
            acc[3][5] = fma2_(k3, wc.y, acc[3][5]);
            acc[0][6] = fma2_(k0, wd.x, acc[0][6]);
            acc[1][6] = fma2_(k1, wd.x, acc[1][6]);
            acc[2][6] = fma2_(k2, wd.x, acc[2][6]);
            acc[3][6] = fma2_(k3, wd.x, acc[3][6]);
            acc[0][7] = fma2_(k0, wd.y, acc[0][7]);
            acc[1][7] = fma2_(k1, wd.y, acc[1][7]);
            acc[2][7] = fma2_(k2, wd.y, acc[2][7]);
            acc[3][7] = fma2_(k3, wd.y, acc[3][7]);
        }
        __syncthreads();
    }

    #pragma unroll
    for (int p = 0; p < 8; p++) {
        float lo[4], hi[4];
        upk2_(acc[0][p], lo[0], hi[0]);
        upk2_(acc[1][p], lo[1], hi[1]);
        upk2_(acc[2][p], lo[2], hi[2]);
        upk2_(acc[3][p], lo[3], hi[3]);
        int q0 = r0 + (qg * 8 + p) * 2;
        *(float4*)&g_part[chunk][(size_t)q0 * UU + ug * 4] =
            make_float4(lo[0], lo[1], lo[2], lo[3]);
        *(float4*)&g_part[chunk][(size_t)(q0 + 1) * UU + ug * 4] =
            make_float4(hi[0], hi[1], hi[2], hi[3]);
    }
}

// ---------------------------------------------------------------------------
// Kernel 5: reduce 32 partials -> context into d_out[0 .. CTX_SIZE)
// ---------------------------------------------------------------------------
__global__ __launch_bounds__(256) void ctx_reduce(float* __restrict__ out)
{
    int i = blockIdx.x * 256 + threadIdx.x;   // float4 index, 32768 total
    float4 s = ((const float4*)g_part[0])[i];
    #pragma unroll
    for (int c = 1; c < NCHUNK; c++) {
        float4 p = ((const float4*)g_part[c])[i];
        s.x += p.x; s.y += p.y; s.z += p.z; s.w += p.w;
    }
    ((float4*)out)[i] = s;
}

extern "C" void kernel_launch(void* const* d_in, const int* in_sizes, int n_in,
                              void* d_out, int out_size)
{
    (void)in_sizes; (void)n_in; (void)out_size;
    const float* dq    = (const float*)d_in[0];   // [4,256,512]
    const float* ev    = (const float*)d_in[1];   // [4,2048,512]
    const float* W1    = (const float*)d_in[2];   // [512,128]
    const float* W2    = (const float*)d_in[3];   // [512,128]
    const float* scale = (const float*)d_in[4];   // [128]
    float* out  = (float*)d_out;                  // context [131072] ++ weights [2097152]
    float* wout = out + CTX_SIZE;

    proj_gemm<<<144, 256>>>(dq, ev, W1, W2);
    scores_kernel<<<dim3(TV / 32, TQ / 32, BB), 128>>>(scale);
    softmax_kernel<<<NROWS_Q, 256>>>(wout);
    ctx_partial<<<dim3(NCHUNK, 16), 128>>>(wout);
    ctx_reduce<<<CTX_SIZE / 4 / 256, 256>>>(out);
}

// round 13
// speedup vs baseline: 1.1689x; 1.0830x over previous
#include <cuda_runtime.h>

#define BB   4
#define TQ   256
#define TV   2048
#define DD   512
#define UU   128
#define NROWS_Q (BB*TQ)          // 1024
#define NROWS_K (BB*TV)          // 8192
#define CTX_SIZE (NROWS_Q*UU)    // 131072
#define NCHUNK 32

typedef unsigned long long ull;

// Scratch (no cudaMalloc allowed)
__device__ float g_eq[NROWS_Q*UU];          // e^{2q}  0.5 MB
__device__ float g_k [NROWS_K*UU];          // raw k   4 MB
__device__ float g_ek[NROWS_K*UU];          // e^{2k}  4 MB
__device__ float g_scores[NROWS_Q*TV];      // 8 MB
__device__ float g_part[NCHUNK][CTX_SIZE];  // 16 MB

__device__ __forceinline__ float ex2f_(float x){ float y; asm("ex2.approx.f32 %0, %1;" : "=f"(y) : "f"(x)); return y; }
__device__ __forceinline__ float rcpf_(float x){ float y; asm("rcp.approx.f32 %0, %1;" : "=f"(y) : "f"(x)); return y; }

// Packed f32x2 (Blackwell): 2x fp32 FMA throughput, only reachable via PTX.
__device__ __forceinline__ ull pk2_(float lo, float hi){ ull r; asm("mov.b64 %0, {%1, %2};" : "=l"(r) : "f"(lo), "f"(hi)); return r; }
__device__ __forceinline__ void upk2_(ull v, float& lo, float& hi){ asm("mov.b64 {%0, %1}, %2;" : "=f"(lo), "=f"(hi) : "l"(v)); }
__device__ __forceinline__ ull fma2_(ull a, ull b, ull c){ ull d; asm("fma.rn.f32x2 %0, %1, %2, %3;" : "=l"(d) : "l"(a), "l"(b), "l"(c)); return d; }
__device__ __forceinline__ ull mul2_(ull a, ull b){ ull d; asm("mul.rn.f32x2 %0, %1, %2;" : "=l"(d) : "l"(a), "l"(b)); return d; }
__device__ __forceinline__ ull add2_(ull a, ull b){ ull d; asm("add.rn.f32x2 %0, %1, %2;" : "=l"(d) : "l"(a), "l"(b)); return d; }
#define ONE2 0x3F8000003F800000ULL

#define C2E 2.88539008177792681f   /* 2*log2(e) */

// ---------------------------------------------------------------------------
// Kernel 1: projections + exp epilogue, packed-FMA, double-buffered smem.
// C[M,128] = A[M,512] @ W[512,128] fp32. bid<16 -> q (store e^{2q} only),
// else -> k (store raw k AND e^{2k}). BM=64, BN=128, BK=16, thread 4m x 8n.
// ---------------------------------------------------------------------------
__global__ __launch_bounds__(256) void proj_gemm(
    const float* __restrict__ dq, const float* __restrict__ ev,
    const float* __restrict__ W1, const float* __restrict__ W2)
{
    __shared__ __align__(16) float As[2][16][68];    // [buf][kk][m]
    __shared__ __align__(16) float Bs[2][16][128];   // [buf][kk][n]

    int bid = blockIdx.x;
    bool isq = (bid < 16);
    const float* A; const float* W; int mbase;
    if (isq) { A = dq; W = W1; mbase = bid * 64; }
    else     { A = ev; W = W2; mbase = (bid - 16) * 64; }

    int t  = threadIdx.x;
    int ty = t >> 4;          // 0..15 (row group)
    int tx = t & 15;          // 0..15 (col group)
    int lr = t >> 2;          // 0..63 (A load row)
    int lc = (t & 3) << 2;    // 0,4,8,12 (A load col quad)
    int br0 = t >> 5;         // B row for i0
    int bc  = (t & 31) << 2;  // B col quad

    ull acc[4][4];
    #pragma unroll
    for (int i = 0; i < 4; i++)
        #pragma unroll
        for (int j = 0; j < 4; j++) acc[i][j] = 0ULL;

    // prologue: tile 0
    {
        float4 av = *(const float4*)&A[(size_t)(mbase + lr) * DD + lc];
        As[0][lc + 0][lr] = av.x; As[0][lc + 1][lr] = av.y;
        As[0][lc + 2][lr] = av.z; As[0][lc + 3][lr] = av.w;
        *(float4*)&Bs[0][br0][bc]     = *(const float4*)&W[(size_t)br0 * UU + bc];
        *(float4*)&Bs[0][br0 + 8][bc] = *(const float4*)&W[(size_t)(br0 + 8) * UU + bc];
    }
    __syncthreads();

    int buf = 0;
    for (int k0 = 0; k0 < DD; k0 += 16, buf ^= 1) {
        float4 nav, nb0, nb1;
        bool more = (k0 + 16 < DD);
        if (more) {
            nav = *(const float4*)&A[(size_t)(mbase + lr) * DD + k0 + 16 + lc];
            nb0 = *(const float4*)&W[(size_t)(k0 + 16 + br0) * UU + bc];
            nb1 = *(const float4*)&W[(size_t)(k0 + 24 + br0) * UU + bc];
        }

        #pragma unroll
        for (int kk = 0; kk < 16; kk++) {
            float4 a4 = *(const float4*)&As[buf][kk][ty * 4];
            ulonglong2 b0 = *(const ulonglong2*)&Bs[buf][kk][tx * 4];
            ulonglong2 b1 = *(const ulonglong2*)&Bs[buf][kk][64 + tx * 4];
            float a[4] = {a4.x, a4.y, a4.z, a4.w};
            #pragma unroll
            for (int i = 0; i < 4; i++) {
                ull ad = pk2_(a[i], a[i]);
                acc[i][0] = fma2_(ad, b0.x, acc[i][0]);
                acc[i][1] = fma2_(ad, b0.y, acc[i][1]);
                acc[i][2] = fma2_(ad, b1.x, acc[i][2]);
                acc[i][3] = fma2_(ad, b1.y, acc[i][3]);
            }
        }

        if (more) {
            int nb = buf ^ 1;
            As[nb][lc + 0][lr] = nav.x; As[nb][lc + 1][lr] = nav.y;
            As[nb][lc + 2][lr] = nav.z; As[nb][lc + 3][lr] = nav.w;
            *(float4*)&Bs[nb][br0][bc]     = nb0;
            *(float4*)&Bs[nb][br0 + 8][bc] = nb1;
        }
        __syncthreads();
    }

    #pragma unroll
    for (int i = 0; i < 4; i++) {
        float c[8];
        upk2_(acc[i][0], c[0], c[1]); upk2_(acc[i][1], c[2], c[3]);
        upk2_(acc[i][2], c[4], c[5]); upk2_(acc[i][3], c[6], c[7]);
        int row = mbase + ty * 4 + i;
        size_t o0 = (size_t)row * UU + tx * 4;
        size_t o1 = o0 + 64;
        float4 e0 = make_float4(ex2f_(c[0]*C2E), ex2f_(c[1]*C2E),
                                ex2f_(c[2]*C2E), ex2f_(c[3]*C2E));
        float4 e1 = make_float4(ex2f_(c[4]*C2E), ex2f_(c[5]*C2E),
                                ex2f_(c[6]*C2E), ex2f_(c[7]*C2E));
        if (isq) {
            *(float4*)&g_eq[o0] = e0;
            *(float4*)&g_eq[o1] = e1;
        } else {
            *(float4*)&g_k[o0] = make_float4(c[0], c[1], c[2], c[3]);
            *(float4*)&g_k[o1] = make_float4(c[4], c[5], c[6], c[7]);
            *(float4*)&g_ek[o0] = e0;
            *(float4*)&g_ek[o1] = e1;
        }
    }
}

// ---------------------------------------------------------------------------
// Kernel 2: scores, factorized exp + pairwise rcp-combine + packed FMA.
//   s0/(1+a0) + s1/(1+a1) = [sab + s0*a1 + s1*a0] / [(1+a0)(1+a1)]
// -> 1 RCP per 2 u. u-swizzled tiles (u0,u2,u1,u3). 128 thr, 32q x 32v,
// thread 2q x 4v with STRIDED row ownership: v rows vg+8*vj, q rows
// qg+16*qi. Row stride 528B = 16 mod 128 -> the 8 vg's k-loads hit 8
// distinct bank-quads (conflict-free; was 4-way with blocked rows).
// score' = -2*sum (const Sum(scale) shift dropped; softmax shift-invariant).
// ---------------------------------------------------------------------------
__global__ __launch_bounds__(128, 6) void scores_kernel(const float* __restrict__ scale)
{
    __shared__ __align__(16) float Qs[32][132];    // stride 132: 16B-aligned rows
    __shared__ __align__(16) float Ks[32][132];
    __shared__ __align__(8)  float2 Sa[32], Sb[32], Sab[32];

    int b  = blockIdx.z;
    int qt = blockIdx.y;
    int vt = blockIdx.x;
    int t  = threadIdx.x;

    const float* qg_ = g_eq + (size_t)(b * TQ + qt * 32) * UU;
    const float* kg_ = g_ek + (size_t)(b * TV + vt * 32) * UU;

    #pragma unroll
    for (int j = 0; j < 8; j++) {
        int i = t + j * 128;
        int r = i >> 5, c = (i & 31) << 2;
        float4 x = *(const float4*)&qg_[(size_t)r * UU + c];
        *(float4*)&Qs[r][c] = make_float4(x.x, x.z, x.y, x.w);   // u-swizzle
        float4 y = *(const float4*)&kg_[(size_t)r * UU + c];
        *(float4*)&Ks[r][c] = make_float4(y.x, y.z, y.y, y.w);
    }
    if (t < 32) {
        float4 s = *(const float4*)&scale[t * 4];
        Sa[t]  = make_float2(s.x, s.z);
        Sb[t]  = make_float2(s.y, s.w);
        Sab[t] = make_float2(s.x + s.y, s.z + s.w);
    }
    __syncthreads();

    int vg = t & 7;           // v rows vg + 8*vj
    int qg = t >> 3;          // q rows qg + 16*qi

    ull acc[2][4];
    #pragma unroll
    for (int i = 0; i < 2; i++)
        #pragma unroll
        for (int j = 0; j < 4; j++) acc[i][j] = 0ULL;

    #pragma unroll 2
    for (int uq = 0; uq < 32; uq++) {
        ull sa  = *(const ull*)&Sa[uq];
        ull sb  = *(const ull*)&Sb[uq];
        ull sab = *(const ull*)&Sab[uq];
        ulonglong2 k4[4];
        #pragma unroll
        for (int vj = 0; vj < 4; vj++)
            k4[vj] = *(const ulonglong2*)&Ks[vg + 8 * vj][uq * 4];
        #pragma unroll
        for (int qi = 0; qi < 2; qi++) {
            ulonglong2 q4 = *(const ulonglong2*)&Qs[qg + 16 * qi][uq * 4];
            #pragma unroll
            for (int vj = 0; vj < 4; vj++) {
                ull A = mul2_(q4.x, k4[vj].x);    // (a_u0, a_u2)
                ull B = mul2_(q4.y, k4[vj].y);    // (a_u1, a_u3)
                ull U = add2_(A, ONE2);
                ull P = fma2_(U, B, U);           // (1+a)(1+b)
                ull N = fma2_(sb, A, sab);
                N = fma2_(sa, B, N);
                float pl, ph; upk2_(P, pl, ph);
                ull R = pk2_(rcpf_(pl), rcpf_(ph));
                acc[qi][vj] = fma2_(N, R, acc[qi][vj]);
            }
        }
    }

    #pragma unroll
    for (int qi = 0; qi < 2; qi++) {
        float* out = g_scores + (size_t)(b * TQ + qt * 32 + qg + 16 * qi) * TV + vt * 32 + vg;
        #pragma unroll
        for (int vj = 0; vj < 4; vj++) {
            float lo, hi; upk2_(acc[qi][vj], lo, hi);
            out[8 * vj] = -2.0f * (lo + hi);
        }
    }
}

// ---------------------------------------------------------------------------
// Kernel 3: row softmax over Tv=2048. One block per (b,q) row.
// ---------------------------------------------------------------------------
__global__ __launch_bounds__(256) void softmax_kernel(float* __restrict__ wout)
{
    __shared__ float red[8];
    int row = blockIdx.x;
    int t   = threadIdx.x;

    const float4* in4 = (const float4*)(g_scores + (size_t)row * TV);
    float4 a = in4[t];
    float4 b = in4[t + 256];

    float m = fmaxf(fmaxf(fmaxf(a.x, a.y), fmaxf(a.z, a.w)),
                    fmaxf(fmaxf(b.x, b.y), fmaxf(b.z, b.w)));
    #pragma unroll
    for (int off = 16; off; off >>= 1)
        m = fmaxf(m, __shfl_xor_sync(0xffffffffu, m, off));
    if ((t & 31) == 0) red[t >> 5] = m;
    __syncthreads();
    m = red[0];
    #pragma unroll
    for (int i = 1; i < 8; i++) m = fmaxf(m, red[i]);

    const float L2E = 1.44269504088896341f;
    float e0 = ex2f_((a.x - m) * L2E), e1 = ex2f_((a.y - m) * L2E);
    float e2 = ex2f_((a.z - m) * L2E), e3 = ex2f_((a.w - m) * L2E);
    float e4 = ex2f_((b.x - m) * L2E), e5 = ex2f_((b.y - m) * L2E);
    float e6 = ex2f_((b.z - m) * L2E), e7 = ex2f_((b.w - m) * L2E);
    float s = ((e0 + e1) + (e2 + e3)) + ((e4 + e5) + (e6 + e7));
    #pragma unroll
    for (int off = 16; off; off >>= 1)
        s += __shfl_xor_sync(0xffffffffu, s, off);
    __syncthreads();
    if ((t & 31) == 0) red[t >> 5] = s;
    __syncthreads();
    float tot = 0.0f;
    #pragma unroll
    for (int i = 0; i < 8; i++) tot += red[i];
    float inv = rcpf_(tot);

    float4* o4 = (float4*)(wout + (size_t)row * TV);
    o4[t]       = make_float4(e0 * inv, e1 * inv, e2 * inv, e3 * inv);
    o4[t + 256] = make_float4(e4 * inv, e5 * inv, e6 * inv, e7 * inv);
}

// ---------------------------------------------------------------------------
// Kernel 4: context partials. ctx[b,q,u] = sum_v w[b,q,v]*k[b,v,u].
// Grid (32 v-chunks of 64, 16 q-tiles of 64) = 512 blocks, 256 thr:
// WARP = q-group: warp w owns q rows w*8..w*8+7 (4 q-pairs), all 128 u;
// lane = u-quad. -> w-loads are pure warp broadcasts (1 cyc), k-load is
// one clean 512B row (4 wf). Per warp-v: 6 LDS-cyc vs 32 fma2 -> FMA-bound.
// 16 packed accs (~70 regs) + launch_bounds(256,3) -> 24 warps/SM.
// ---------------------------------------------------------------------------
__global__ __launch_bounds__(256, 3) void ctx_partial(const float* __restrict__ wts)
{
    __shared__ __align__(16) float Ks2[32][128];   // [v][u] 16KB
    __shared__ __align__(16) ull   Wp[32][34];     // [v][qpair 0..31]; 272B rows

    int chunk = blockIdx.x;          // 0..31 -> v in [chunk*64, +64)
    int rt    = blockIdx.y;          // 0..15 -> q rows rt*64..+63
    int r0    = rt * 64;             // global row base (b*256+q)
    int bbb   = r0 >> 8;             // batch
    int t     = threadIdx.x;
    int ug    = t & 31;              // lane = u-quad (u = ug*4..+3)
    int qg    = t >> 5;              // warp id = q-group (q-pairs qg*4..+3)

    ull acc[4][4];                   // [u][qpair]
    #pragma unroll
    for (int u = 0; u < 4; u++)
        #pragma unroll
        for (int p = 0; p < 4; p++) acc[u][p] = 0ULL;

    #pragma unroll 1
    for (int vt = 0; vt < 2; vt++) {
        int vbase = chunk * 64 + vt * 32;
        #pragma unroll
        for (int j = 0; j < 4; j++) {
            int i = t + j * 256;                  // 0..1023
            int v = i >> 5, c = (i & 31) << 2;
            *(float4*)&Ks2[v][c] =
                *(const float4*)&g_k[(size_t)(bbb * TV + vbase + v) * UU + c];
        }
        #pragma unroll
        for (int j = 0; j < 4; j++) {
            int i = t + j * 256;                  // 0..1023
            int qp = i >> 5, v = i & 31;          // qp 0..31, v 0..31
            const float* wp = &wts[(size_t)(r0 + qp * 2) * TV + vbase + v];
            Wp[v][qp] = pk2_(wp[0], wp[TV]);
        }
        __syncthreads();

        #pragma unroll 4
        for (int v = 0; v < 32; v++) {
            float4 kf = *(const float4*)&Ks2[v][ug * 4];
            ull k0 = pk2_(kf.x, kf.x), k1 = pk2_(kf.y, kf.y);
            ull k2 = pk2_(kf.z, kf.z), k3 = pk2_(kf.w, kf.w);
            ulonglong2 wa = *(const ulonglong2*)&Wp[v][qg * 4];      // warp-broadcast
            ulonglong2 wb = *(const ulonglong2*)&Wp[v][qg * 4 + 2];  // warp-broadcast
            acc[0][0] = fma2_(k0, wa.x, acc[0][0]);
            acc[1][0] = fma2_(k1, wa.x, acc[1][0]);
            acc[2][0] = fma2_(k2, wa.x, acc[2][0]);
            acc[3][0] = fma2_(k3, wa.x, acc[3][0]);
            acc[0][1] = fma2_(k0, wa.y, acc[0][1]);
            acc[1][1] = fma2_(k1, wa.y, acc[1][1]);
            acc[2][1] = fma2_(k2, wa.y, acc[2][1]);
            acc[3][1] = fma2_(k3, wa.y, acc[3][1]);
            acc[0][2] = fma2_(k0, wb.x, acc[0][2]);
            acc[1][2] = fma2_(k1, wb.x, acc[1][2]);
            acc[2][2] = fma2_(k2, wb.x, acc[2][2]);
            acc[3][2] = fma2_(k3, wb.x, acc[3][2]);
            acc[0][3] = fma2_(k0, wb.y, acc[0][3]);
            acc[1][3] = fma2_(k1, wb.y, acc[1][3]);
            acc[2][3] = fma2_(k2, wb.y, acc[2][3]);
            acc[3][3] = fma2_(k3, wb.y, acc[3][3]);
        }
        __syncthreads();
    }

    #pragma unroll
    for (int p = 0; p < 4; p++) {
        float lo[4], hi[4];
        upk2_(acc[0][p], lo[0], hi[0]);
        upk2_(acc[1][p], lo[1], hi[1]);
        upk2_(acc[2][p], lo[2], hi[2]);
        upk2_(acc[3][p], lo[3], hi[3]);
        int q0 = r0 + (qg * 4 + p) * 2;
        *(float4*)&g_part[chunk][(size_t)q0 * UU + ug * 4] =
            make_float4(lo[0], lo[1], lo[2], lo[3]);
        *(float4*)&g_part[chunk][(size_t)(q0 + 1) * UU + ug * 4] =
            make_float4(hi[0], hi[1], hi[2], hi[3]);
    }
}

// ---------------------------------------------------------------------------
// Kernel 5: reduce 32 partials -> context into d_out[0 .. CTX_SIZE)
// ---------------------------------------------------------------------------
__global__ __launch_bounds__(256) void ctx_reduce(float* __restrict__ out)
{
    int i = blockIdx.x * 256 + threadIdx.x;   // float4 index, 32768 total
    float4 s = ((const float4*)g_part[0])[i];
    #pragma unroll
    for (int c = 1; c < NCHUNK; c++) {
        float4 p = ((const float4*)g_part[c])[i];
        s.x += p.x; s.y += p.y; s.z += p.z; s.w += p.w;
    }
    ((float4*)out)[i] = s;
}

extern "C" void kernel_launch(void* const* d_in, const int* in_sizes, int n_in,
                              void* d_out, int out_size)
{
    (void)in_sizes; (void)n_in; (void)out_size;
    const float* dq    = (const float*)d_in[0];   // [4,256,512]
    const float* ev    = (const float*)d_in[1];   // [4,2048,512]
    const float* W1    = (const float*)d_in[2];   // [512,128]
    const float* W2    = (const float*)d_in[3];   // [512,128]
    const float* scale = (const float*)d_in[4];   // [128]
    float* out  = (float*)d_out;                  // context [131072] ++ weights [2097152]
    float* wout = out + CTX_SIZE;

    proj_gemm<<<144, 256>>>(dq, ev, W1, W2);
    scores_kernel<<<dim3(TV / 32, TQ / 32, BB), 128>>>(scale);
    softmax_kernel<<<NROWS_Q, 256>>>(wout);
    ctx_partial<<<dim3(NCHUNK, 16), 256>>>(wout);
    ctx_reduce<<<CTX_SIZE / 4 / 256, 256>>>(out);
}

// round 14
// speedup vs baseline: 1.1698x; 1.0008x over previous
#include <cuda_runtime.h>

#define BB   4
#define TQ   256
#define TV   2048
#define DD   512
#define UU   128
#define NROWS_Q (BB*TQ)          // 1024
#define NROWS_K (BB*TV)          // 8192
#define CTX_SIZE (NROWS_Q*UU)    // 131072
#define NCHUNK 32

typedef unsigned long long ull;

// Scratch (no cudaMalloc allowed)
__device__ float g_eq[NROWS_Q*UU];          // e^{2q}  0.5 MB
__device__ float g_k [NROWS_K*UU];          // raw k   4 MB
__device__ float g_ek[NROWS_K*UU];          // e^{2k}  4 MB
__device__ float g_scores[NROWS_Q*TV];      // 8 MB
__device__ float g_part[NCHUNK][CTX_SIZE];  // 16 MB

__device__ __forceinline__ float ex2f_(float x){ float y; asm("ex2.approx.f32 %0, %1;" : "=f"(y) : "f"(x)); return y; }
__device__ __forceinline__ float rcpf_(float x){ float y; asm("rcp.approx.f32 %0, %1;" : "=f"(y) : "f"(x)); return y; }

// Packed f32x2 (Blackwell): 2x fp32 FMA throughput, only reachable via PTX.
__device__ __forceinline__ ull pk2_(float lo, float hi){ ull r; asm("mov.b64 %0, {%1, %2};" : "=l"(r) : "f"(lo), "f"(hi)); return r; }
__device__ __forceinline__ void upk2_(ull v, float& lo, float& hi){ asm("mov.b64 {%0, %1}, %2;" : "=f"(lo), "=f"(hi) : "l"(v)); }
__device__ __forceinline__ ull fma2_(ull a, ull b, ull c){ ull d; asm("fma.rn.f32x2 %0, %1, %2, %3;" : "=l"(d) : "l"(a), "l"(b), "l"(c)); return d; }
__device__ __forceinline__ ull mul2_(ull a, ull b){ ull d; asm("mul.rn.f32x2 %0, %1, %2;" : "=l"(d) : "l"(a), "l"(b)); return d; }
__device__ __forceinline__ ull add2_(ull a, ull b){ ull d; asm("add.rn.f32x2 %0, %1, %2;" : "=l"(d) : "l"(a), "l"(b)); return d; }
#define ONE2 0x3F8000003F800000ULL

#define C2E 2.88539008177792681f   /* 2*log2(e) */

// Dynamic smem budget for scores_kernel: Qs 32x132 + Ks 64x132 + 3x32 float2
#define SC_SMEM (96*132*4 + 3*32*8)   // 51456 bytes

// ---------------------------------------------------------------------------
// Kernel 1: projections + exp epilogue, packed-FMA, double-buffered smem.
// C[M,128] = A[M,512] @ W[512,128] fp32. bid<16 -> q (store e^{2q} only),
// else -> k (store raw k AND e^{2k}). BM=64, BN=128, BK=16, thread 4m x 8n.
// ---------------------------------------------------------------------------
__global__ __launch_bounds__(256) void proj_gemm(
    const float* __restrict__ dq, const float* __restrict__ ev,
    const float* __restrict__ W1, const float* __restrict__ W2)
{
    __shared__ __align__(16) float As[2][16][68];    // [buf][kk][m]
    __shared__ __align__(16) float Bs[2][16][128];   // [buf][kk][n]

    int bid = blockIdx.x;
    bool isq = (bid < 16);
    const float* A; const float* W; int mbase;
    if (isq) { A = dq; W = W1; mbase = bid * 64; }
    else     { A = ev; W = W2; mbase = (bid - 16) * 64; }

    int t  = threadIdx.x;
    int ty = t >> 4;          // 0..15 (row group)
    int tx = t & 15;          // 0..15 (col group)
    int lr = t >> 2;          // 0..63 (A load row)
    int lc = (t & 3) << 2;    // 0,4,8,12 (A load col quad)
    int br0 = t >> 5;         // B row for i0
    int bc  = (t & 31) << 2;  // B col quad

    ull acc[4][4];
    #pragma unroll
    for (int i = 0; i < 4; i++)
        #pragma unroll
        for (int j = 0; j < 4; j++) acc[i][j] = 0ULL;

    // prologue: tile 0
    {
        float4 av = *(const float4*)&A[(size_t)(mbase + lr) * DD + lc];
        As[0][lc + 0][lr] = av.x; As[0][lc + 1][lr] = av.y;
        As[0][lc + 2][lr] = av.z; As[0][lc + 3][lr] = av.w;
        *(float4*)&Bs[0][br0][bc]     = *(const float4*)&W[(size_t)br0 * UU + bc];
        *(float4*)&Bs[0][br0 + 8][bc] = *(const float4*)&W[(size_t)(br0 + 8) * UU + bc];
    }
    __syncthreads();

    int buf = 0;
    for (int k0 = 0; k0 < DD; k0 += 16, buf ^= 1) {
        float4 nav, nb0, nb1;
        bool more = (k0 + 16 < DD);
        if (more) {
            nav = *(const float4*)&A[(size_t)(mbase + lr) * DD + k0 + 16 + lc];
            nb0 = *(const float4*)&W[(size_t)(k0 + 16 + br0) * UU + bc];
            nb1 = *(const float4*)&W[(size_t)(k0 + 24 + br0) * UU + bc];
        }

        #pragma unroll
        for (int kk = 0; kk < 16; kk++) {
            float4 a4 = *(const float4*)&As[buf][kk][ty * 4];
            ulonglong2 b0 = *(const ulonglong2*)&Bs[buf][kk][tx * 4];
            ulonglong2 b1 = *(const ulonglong2*)&Bs[buf][kk][64 + tx * 4];
            float a[4] = {a4.x, a4.y, a4.z, a4.w};
            #pragma unroll
            for (int i = 0; i < 4; i++) {
                ull ad = pk2_(a[i], a[i]);
                acc[i][0] = fma2_(ad, b0.x, acc[i][0]);
                acc[i][1] = fma2_(ad, b0.y, acc[i][1]);
                acc[i][2] = fma2_(ad, b1.x, acc[i][2]);
                acc[i][3] = fma2_(ad, b1.y, acc[i][3]);
            }
        }

        if (more) {
            int nb = buf ^ 1;
            As[nb][lc + 0][lr] = nav.x; As[nb][lc + 1][lr] = nav.y;
            As[nb][lc + 2][lr] = nav.z; As[nb][lc + 3][lr] = nav.w;
            *(float4*)&Bs[nb][br0][bc]     = nb0;
            *(float4*)&Bs[nb][br0 + 8][bc] = nb1;
        }
        __syncthreads();
    }

    #pragma unroll
    for (int i = 0; i < 4; i++) {
        float c[8];
        upk2_(acc[i][0], c[0], c[1]); upk2_(acc[i][1], c[2], c[3]);
        upk2_(acc[i][2], c[4], c[5]); upk2_(acc[i][3], c[6], c[7]);
        int row = mbase + ty * 4 + i;
        size_t o0 = (size_t)row * UU + tx * 4;
        size_t o1 = o0 + 64;
        float4 e0 = make_float4(ex2f_(c[0]*C2E), ex2f_(c[1]*C2E),
                                ex2f_(c[2]*C2E), ex2f_(c[3]*C2E));
        float4 e1 = make_float4(ex2f_(c[4]*C2E), ex2f_(c[5]*C2E),
                                ex2f_(c[6]*C2E), ex2f_(c[7]*C2E));
        if (isq) {
            *(float4*)&g_eq[o0] = e0;
            *(float4*)&g_eq[o1] = e1;
        } else {
            *(float4*)&g_k[o0] = make_float4(c[0], c[1], c[2], c[3]);
            *(float4*)&g_k[o1] = make_float4(c[4], c[5], c[6], c[7]);
            *(float4*)&g_ek[o0] = e0;
            *(float4*)&g_ek[o1] = e1;
        }
    }
}

// ---------------------------------------------------------------------------
// Kernel 2: scores, factorized exp + pairwise rcp-combine + packed FMA.
//   s0/(1+a0) + s1/(1+a1) = [sab + s0*a1 + s1*a0] / [(1+a0)(1+a1)]
// -> 1 RCP per 2 u. u-swizzled tiles (u0,u2,u1,u3). 32q x 64v tile in
// DYNAMIC smem (51.4KB > 48KB static limit), 128 thr, thread 4q x 4v
// strided (v rows vg+16*vj, q rows qg+8*qi -> addresses 16*r mod 128,
// conflict-free-or-2-way LDS). k4/q4/scale loads amortized 2x vs R13;
// block count halved to 1024. -2 folded into scale constants.
// ---------------------------------------------------------------------------
__global__ __launch_bounds__(128) void scores_kernel(const float* __restrict__ scale)
{
    extern __shared__ __align__(16) float smem_dyn[];
    float (*Qs)[132] = (float(*)[132])smem_dyn;                    // 32 rows
    float (*Ks)[132] = (float(*)[132])(smem_dyn + 32 * 132);       // 64 rows
    float2* Sa  = (float2*)(smem_dyn + 96 * 132);                  // 32
    float2* Sb  = Sa + 32;
    float2* Sab = Sb + 32;

    int b  = blockIdx.z;
    int qt = blockIdx.y;
    int vt = blockIdx.x;
    int t  = threadIdx.x;

    const float* qg_ = g_eq + (size_t)(b * TQ + qt * 32) * UU;
    const float* kg_ = g_ek + (size_t)(b * TV + vt * 64) * UU;

    #pragma unroll
    for (int j = 0; j < 8; j++) {
        int i = t + j * 128;
        int r = i >> 5, c = (i & 31) << 2;
        float4 x = *(const float4*)&qg_[(size_t)r * UU + c];
        *(float4*)&Qs[r][c] = make_float4(x.x, x.z, x.y, x.w);   // u-swizzle
    }
    #pragma unroll
    for (int j = 0; j < 16; j++) {
        int i = t + j * 128;
        int r = i >> 5, c = (i & 31) << 2;
        float4 y = *(const float4*)&kg_[(size_t)r * UU + c];
        *(float4*)&Ks[r][c] = make_float4(y.x, y.z, y.y, y.w);
    }
    if (t < 32) {
        float4 s = *(const float4*)&scale[t * 4];
        Sa[t]  = make_float2(-2.0f * s.x, -2.0f * s.z);
        Sb[t]  = make_float2(-2.0f * s.y, -2.0f * s.w);
        Sab[t] = make_float2(-2.0f * (s.x + s.y), -2.0f * (s.z + s.w));
    }
    __syncthreads();

    int vg = t & 15;          // v rows vg + 16*vj
    int qg = t >> 4;          // q rows qg + 8*qi

    ull acc[4][4];            // [qi][vj]
    #pragma unroll
    for (int i = 0; i < 4; i++)
        #pragma unroll
        for (int j = 0; j < 4; j++) acc[i][j] = 0ULL;

    #pragma unroll 2
    for (int uq = 0; uq < 32; uq++) {
        ull sa  = *(const ull*)&Sa[uq];
        ull sb  = *(const ull*)&Sb[uq];
        ull sab = *(const ull*)&Sab[uq];
        ulonglong2 k4[4];
        #pragma unroll
        for (int vj = 0; vj < 4; vj++)
            k4[vj] = *(const ulonglong2*)&Ks[vg + 16 * vj][uq * 4];
        #pragma unroll
        for (int qi = 0; qi < 4; qi++) {
            ulonglong2 q4 = *(const ulonglong2*)&Qs[qg + 8 * qi][uq * 4];
            #pragma unroll
            for (int vj = 0; vj < 4; vj++) {
                ull A = mul2_(q4.x, k4[vj].x);    // (a_u0, a_u2)
                ull B = mul2_(q4.y, k4[vj].y);    // (a_u1, a_u3)
                ull U = add2_(A, ONE2);
                ull P = fma2_(U, B, U);           // (1+a)(1+b)
                ull N = fma2_(sb, A, sab);
                N = fma2_(sa, B, N);
                float pl, ph; upk2_(P, pl, ph);
                ull R = pk2_(rcpf_(pl), rcpf_(ph));
                acc[qi][vj] = fma2_(N, R, acc[qi][vj]);
            }
        }
    }

    #pragma unroll
    for (int qi = 0; qi < 4; qi++) {
        float* out = g_scores + (size_t)(b * TQ + qt * 32 + qg + 8 * qi) * TV + vt * 64 + vg;
        #pragma unroll
        for (int vj = 0; vj < 4; vj++) {
            float lo, hi; upk2_(acc[qi][vj], lo, hi);
            out[16 * vj] = lo + hi;               // -2*scale already folded
        }
    }
}

// ---------------------------------------------------------------------------
// Kernel 3: row softmax over Tv=2048. One block per (b,q) row.
// ---------------------------------------------------------------------------
__global__ __launch_bounds__(256) void softmax_kernel(float* __restrict__ wout)
{
    __shared__ float red[8];
    int row = blockIdx.x;
    int t   = threadIdx.x;

    const float4* in4 = (const float4*)(g_scores + (size_t)row * TV);
    float4 a = in4[t];
    float4 b = in4[t + 256];

    float m = fmaxf(fmaxf(fmaxf(a.x, a.y), fmaxf(a.z, a.w)),
                    fmaxf(fmaxf(b.x, b.y), fmaxf(b.z, b.w)));
    #pragma unroll
    for (int off = 16; off; off >>= 1)
        m = fmaxf(m, __shfl_xor_sync(0xffffffffu, m, off));
    if ((t & 31) == 0) red[t >> 5] = m;
    __syncthreads();
    m = red[0];
    #pragma unroll
    for (int i = 1; i < 8; i++) m = fmaxf(m, red[i]);

    const float L2E = 1.44269504088896341f;
    float e0 = ex2f_((a.x - m) * L2E), e1 = ex2f_((a.y - m) * L2E);
    float e2 = ex2f_((a.z - m) * L2E), e3 = ex2f_((a.w - m) * L2E);
    float e4 = ex2f_((b.x - m) * L2E), e5 = ex2f_((b.y - m) * L2E);
    float e6 = ex2f_((b.z - m) * L2E), e7 = ex2f_((b.w - m) * L2E);
    float s = ((e0 + e1) + (e2 + e3)) + ((e4 + e5) + (e6 + e7));
    #pragma unroll
    for (int off = 16; off; off >>= 1)
        s += __shfl_xor_sync(0xffffffffu, s, off);
    __syncthreads();
    if ((t & 31) == 0) red[t >> 5] = s;
    __syncthreads();
    float tot = 0.0f;
    #pragma unroll
    for (int i = 0; i < 8; i++) tot += red[i];
    float inv = rcpf_(tot);

    float4* o4 = (float4*)(wout + (size_t)row * TV);
    o4[t]       = make_float4(e0 * inv, e1 * inv, e2 * inv, e3 * inv);
    o4[t + 256] = make_float4(e4 * inv, e5 * inv, e6 * inv, e7 * inv);
}

// ---------------------------------------------------------------------------
// Kernel 4: context partials. ctx[b,q,u] = sum_v w[b,q,v]*k[b,v,u].
// Grid (32 v-chunks of 64, 16 q-tiles of 64) = 512 blocks, 256 thr:
// WARP = q-group: warp w owns q rows w*8..w*8+7 (4 q-pairs), all 128 u;
// lane = u-quad. w-loads are warp broadcasts; k-load one clean 512B row.
// ---------------------------------------------------------------------------
__global__ __launch_bounds__(256, 3) void ctx_partial(const float* __restrict__ wts)
{
    __shared__ __align__(16) float Ks2[32][128];   // [v][u] 16KB
    __shared__ __align__(16) ull   Wp[32][34];     // [v][qpair 0..31]; 272B rows

    int chunk = blockIdx.x;          // 0..31 -> v in [chunk*64, +64)
    int rt    = blockIdx.y;          // 0..15 -> q rows rt*64..+63
    int r0    = rt * 64;             // global row base (b*256+q)
    int bbb   = r0 >> 8;             // batch
    int t     = threadIdx.x;
    int ug    = t & 31;              // lane = u-quad (u = ug*4..+3)
    int qg    = t >> 5;              // warp id = q-group (q-pairs qg*4..+3)

    ull acc[4][4];                   // [u][qpair]
    #pragma unroll
    for (int u = 0; u < 4; u++)
        #pragma unroll
        for (int p = 0; p < 4; p++) acc[u][p] = 0ULL;

    #pragma unroll 1
    for (int vt = 0; vt < 2; vt++) {
        int vbase = chunk * 64 + vt * 32;
        #pragma unroll
        for (int j = 0; j < 4; j++) {
            int i = t + j * 256;                  // 0..1023
            int v = i >> 5, c = (i & 31) << 2;
            *(float4*)&Ks2[v][c] =
                *(const float4*)&g_k[(size_t)(bbb * TV + vbase + v) * UU + c];
        }
        #pragma unroll
        for (int j = 0; j < 4; j++) {
            int i = t + j * 256;                  // 0..1023
            int qp = i >> 5, v = i & 31;          // qp 0..31, v 0..31
            const float* wp = &wts[(size_t)(r0 + qp * 2) * TV + vbase + v];
            Wp[v][qp] = pk2_(wp[0], wp[TV]);
        }
        __syncthreads();

        #pragma unroll 4
        for (int v = 0; v < 32; v++) {
            float4 kf = *(const float4*)&Ks2[v][ug * 4];
            ull k0 = pk2_(kf.x, kf.x), k1 = pk2_(kf.y, kf.y);
            ull k2 = pk2_(kf.z, kf.z), k3 = pk2_(kf.w, kf.w);
            ulonglong2 wa = *(const ulonglong2*)&Wp[v][qg * 4];      // warp-broadcast
            ulonglong2 wb = *(const ulonglong2*)&Wp[v][qg * 4 + 2];  // warp-broadcast
            acc[0][0] = fma2_(k0, wa.x, acc[0][0]);
            acc[1][0] = fma2_(k1, wa.x, acc[1][0]);
            acc[2][0] = fma2_(k2, wa.x, acc[2][0]);
            acc[3][0] = fma2_(k3, wa.x, acc[3][0]);
            acc[0][1] = fma2_(k0, wa.y, acc[0][1]);
            acc[1][1] = fma2_(k1, wa.y, acc[1][1]);
            acc[2][1] = fma2_(k2, wa.y, acc[2][1]);
            acc[3][1] = fma2_(k3, wa.y, acc[3][1]);
            acc[0][2] = fma2_(k0, wb.x, acc[0][2]);
            acc[1][2] = fma2_(k1, wb.x, acc[1][2]);
            acc[2][2] = fma2_(k2, wb.x, acc[2][2]);
            acc[3][2] = fma2_(k3, wb.x, acc[3][2]);
            acc[0][3] = fma2_(k0, wb.y, acc[0][3]);
            acc[1][3] = fma2_(k1, wb.y, acc[1][3]);
            acc[2][3] = fma2_(k2, wb.y, acc[2][3]);
            acc[3][3] = fma2_(k3, wb.y, acc[3][3]);
        }
        __syncthreads();
    }

    #pragma unroll
    for (int p = 0; p < 4; p++) {
        float lo[4], hi[4];
        upk2_(acc[0][p], lo[0], hi[0]);
        upk2_(acc[1][p], lo[1], hi[1]);
        upk2_(acc[2][p], lo[2], hi[2]);
        upk2_(acc[3][p], lo[3], hi[3]);
        int q0 = r0 + (qg * 4 + p) * 2;
        *(float4*)&g_part[chunk][(size_t)q0 * UU + ug * 4] =
            make_float4(lo[0], lo[1], lo[2], lo[3]);
        *(float4*)&g_part[chunk][(size_t)(q0 + 1) * UU + ug * 4] =
            make_float4(hi[0], hi[1], hi[2], hi[3]);
    }
}

// ---------------------------------------------------------------------------
// Kernel 5: reduce 32 partials -> context into d_out[0 .. CTX_SIZE)
// ---------------------------------------------------------------------------
__global__ __launch_bounds__(256) void ctx_reduce(float* __restrict__ out)
{
    int i = blockIdx.x * 256 + threadIdx.x;   // float4 index, 32768 total
    float4 s = ((const float4*)g_part[0])[i];
    #pragma unroll
    for (int c = 1; c < NCHUNK; c++) {
        float4 p = ((const float4*)g_part[c])[i];
        s.x += p.x; s.y += p.y; s.z += p.z; s.w += p.w;
    }
    ((float4*)out)[i] = s;
}

extern "C" void kernel_launch(void* const* d_in, const int* in_sizes, int n_in,
                              void* d_out, int out_size)
{
    (void)in_sizes; (void)n_in; (void)out_size;
    const float* dq    = (const float*)d_in[0];   // [4,256,512]
    const float* ev    = (const float*)d_in[1];   // [4,2048,512]
    const float* W1    = (const float*)d_in[2];   // [512,128]
    const float* W2    = (const float*)d_in[3];   // [512,128]
    const float* scale = (const float*)d_in[4];   // [128]
    float* out  = (float*)d_out;                  // context [131072] ++ weights [2097152]
    float* wout = out + CTX_SIZE;

    static int smem_set = 0;
    if (!smem_set) {
        cudaFuncSetAttribute(scores_kernel,
                             cudaFuncAttributeMaxDynamicSharedMemorySize, SC_SMEM);
        smem_set = 1;
    }

    proj_gemm<<<144, 256>>>(dq, ev, W1, W2);
    scores_kernel<<<dim3(TV / 64, TQ / 32, BB), 128, SC_SMEM>>>(scale);
    softmax_kernel<<<NROWS_Q, 256>>>(wout);
    ctx_partial<<<dim3(NCHUNK, 16), 256>>>(wout);
    ctx_reduce<<<CTX_SIZE / 4 / 256, 256>>>(out);
}